// round 16
// baseline (speedup 1.0000x reference)
#include <cuda_runtime.h>
#include <cuda_bf16.h>
#include <cstdint>

// Problem constants (fixed shapes)
#define BATCH 2
#define CDIM 128
#define NPIX 65536          // 256*256
#define LAST0 64512         // (chunks-1)*M
#define NROWBLK 4096        // NPIX/16
#define SCALE_L2 20.6099075f   // 1/(0.07 * ln2)
#define LN2F 0.6931471805599453f

typedef unsigned long long u64;

// ---------------- scratch (device globals: no allocations allowed) ----------
__device__ uint4    g_Apack[BATCH * NROWBLK * 8 * 32];   // 33.5 MB, bf16 mma A fragments
__device__ uint4    g_Bpack[BATCH * 16 * 1024];          // 512 KB: [b][it][(nb*4+s2)*32+lane]
__device__ float    g_inv2[BATCH * NPIX];
__device__ float    g_posl2[BATCH * NPIX];               // pos logit in log2 domain
__device__ double   g_acc;
__device__ unsigned g_done;

// ---------------- helpers ----------------
__device__ __forceinline__ unsigned pack2(float lo, float hi) {
    __nv_bfloat162 h = __floats2bfloat162_rn(lo, hi);
    return *reinterpret_cast<unsigned*>(&h);
}
__device__ __forceinline__ float ex2(float x) {
    float e; asm("ex2.approx.f32 %0,%1;" : "=f"(e) : "f"(x)); return e;
}
// unpack bf16x2, scale both halves by f (fp32), repack
__device__ __forceinline__ unsigned scl2(unsigned u, float f) {
    float lo = __int_as_float(u << 16) * f;
    float hi = __int_as_float(u & 0xFFFF0000u) * f;
    return pack2(lo, hi);
}

#define CP16(dst, src) asm volatile("cp.async.ca.shared.global [%0],[%1],16;\n" :: "r"(dst), "l"(src))
#define CPCOMMIT()     asm volatile("cp.async.commit_group;\n")
#define CPWAIT0()      asm volatile("cp.async.wait_group 0;\n")

#define MMA_BF16(c0, c1, c2, c3, av, b0, b1)                               \
    asm volatile(                                                           \
        "mma.sync.aligned.m16n8k16.row.col.f32.bf16.bf16.f32 "             \
        "{%0,%1,%2,%3}, {%4,%5,%6,%7}, {%8,%9}, {%0,%1,%2,%3};\n"          \
        : "+f"(c0), "+f"(c1), "+f"(c2), "+f"(c3)                            \
        : "r"((av).x), "r"((av).y), "r"((av).z), "r"((av).w),               \
          "r"(b0), "r"(b1))

// epilogue directly on chain accumulators (previous nb's completed results).
// MUFU ex2.approx for the exp sums (exact 1.0 at masked-out x==0).
#define EPILOGUE_CH(lcp) do {                                               \
    float v0 = (lr0 != (lcp).x) ? (eA0 + oA0) : 0.f;                        \
    float v1 = (lr0 != (lcp).y) ? (eA1 + oA1) : 0.f;                        \
    float v2 = (lr1 != (lcp).x) ? (eA2 + oA2) : 0.f;                        \
    float v3 = (lr1 != (lcp).y) ? (eA3 + oA3) : 0.f;                        \
    float v4 = (lr2 != (lcp).x) ? (eB0 + oB0) : 0.f;                        \
    float v5 = (lr2 != (lcp).y) ? (eB1 + oB1) : 0.f;                        \
    float v6 = (lr3 != (lcp).x) ? (eB2 + oB2) : 0.f;                        \
    float v7 = (lr3 != (lcp).y) ? (eB3 + oB3) : 0.f;                        \
    sxw += ((v0 + v1) + (v2 + v3)) + ((v4 + v5) + (v6 + v7));               \
    sep0 += ex2(v0) + ex2(v1);                                              \
    sep1 += ex2(v2) + ex2(v3);                                              \
    sep2 += ex2(v4) + ex2(v5);                                              \
    sep3 += ex2(v6) + ex2(v7);                                              \
} while (0)

// ---------------- kernel 1: normalize z1/z2 (vectorized), pos, pack A fragments -----
// 128-pixel x 128-channel tiles; all global loads are float4 along the pixel dim.
__global__ void __launch_bounds__(256) k_norm_pack(const float* __restrict__ z1,
                                                   const float* __restrict__ z2) {
    if (blockIdx.x == 0 && blockIdx.y == 0 && threadIdx.x == 0) {
        g_acc = 0.0;
        g_done = 0u;
    }
    const int b   = blockIdx.y;
    const int p0  = blockIdx.x * 128;
    const int tid = threadIdx.x;
    const int pg  = tid & 31;    // pixel group: pixels p0 + pg*4 .. +3
    const int cg  = tid >> 5;    // channel group: channels cg*16 .. +15

    __shared__ unsigned s1u[64][136];    // raw z1 bf16x2 pairs [ch-pair][pixel]
    __shared__ float    red[3][8][132];  // per-cg partial ss1/ss2/dot per pixel
    __shared__ float    invsm[128];

    const size_t base = (size_t)b * CDIM * NPIX + p0 + pg * 4;

    float4 ss1 = make_float4(0.f, 0.f, 0.f, 0.f);
    float4 ss2 = make_float4(0.f, 0.f, 0.f, 0.f);
    float4 dt  = make_float4(0.f, 0.f, 0.f, 0.f);
#pragma unroll
    for (int jp = 0; jp < 8; jp++) {
        int c0 = cg * 16 + jp * 2;
        float4 u0 = *(const float4*)(z1 + base + (size_t)(c0    ) * NPIX);
        float4 u1 = *(const float4*)(z1 + base + (size_t)(c0 + 1) * NPIX);
        float4 w0 = *(const float4*)(z2 + base + (size_t)(c0    ) * NPIX);
        float4 w1 = *(const float4*)(z2 + base + (size_t)(c0 + 1) * NPIX);
        ss1.x = fmaf(u0.x, u0.x, ss1.x); ss1.x = fmaf(u1.x, u1.x, ss1.x);
        ss1.y = fmaf(u0.y, u0.y, ss1.y); ss1.y = fmaf(u1.y, u1.y, ss1.y);
        ss1.z = fmaf(u0.z, u0.z, ss1.z); ss1.z = fmaf(u1.z, u1.z, ss1.z);
        ss1.w = fmaf(u0.w, u0.w, ss1.w); ss1.w = fmaf(u1.w, u1.w, ss1.w);
        ss2.x = fmaf(w0.x, w0.x, ss2.x); ss2.x = fmaf(w1.x, w1.x, ss2.x);
        ss2.y = fmaf(w0.y, w0.y, ss2.y); ss2.y = fmaf(w1.y, w1.y, ss2.y);
        ss2.z = fmaf(w0.z, w0.z, ss2.z); ss2.z = fmaf(w1.z, w1.z, ss2.z);
        ss2.w = fmaf(w0.w, w0.w, ss2.w); ss2.w = fmaf(w1.w, w1.w, ss2.w);
        dt.x  = fmaf(u0.x, w0.x, dt.x);  dt.x  = fmaf(u1.x, w1.x, dt.x);
        dt.y  = fmaf(u0.y, w0.y, dt.y);  dt.y  = fmaf(u1.y, w1.y, dt.y);
        dt.z  = fmaf(u0.z, w0.z, dt.z);  dt.z  = fmaf(u1.z, w1.z, dt.z);
        dt.w  = fmaf(u0.w, w0.w, dt.w);  dt.w  = fmaf(u1.w, w1.w, dt.w);
        uint4 o;
        o.x = pack2(u0.x, u1.x);
        o.y = pack2(u0.y, u1.y);
        o.z = pack2(u0.z, u1.z);
        o.w = pack2(u0.w, u1.w);
        *(uint4*)&s1u[cg * 8 + jp][pg * 4] = o;
    }
    *(float4*)&red[0][cg][pg * 4] = ss1;
    *(float4*)&red[1][cg][pg * 4] = ss2;
    *(float4*)&red[2][cg][pg * 4] = dt;
    __syncthreads();

    if (tid < 128) {
        float a = 0.f, bb = 0.f, d = 0.f;
#pragma unroll
        for (int g = 0; g < 8; g++) {
            a += red[0][g][tid]; bb += red[1][g][tid]; d += red[2][g][tid];
        }
        float inv1 = 1.f / fmaxf(sqrtf(a),  1e-12f);
        float inv2 = 1.f / fmaxf(sqrtf(bb), 1e-12f);
        invsm[tid] = inv1;
        g_inv2 [b * NPIX + p0 + tid] = inv2;
        g_posl2[b * NPIX + p0 + tid] = d * inv1 * inv2 * SCALE_L2;  // pos in log2 domain
    }
    __syncthreads();

    // Pack A into mma fragment order: 2048 uint4 per tile by 256 threads.
#pragma unroll
    for (int q = 0; q < 8; q++) {
        int wi   = tid + 256 * q;        // 0..2047
        int rbl  = wi >> 8;              // rowblock 0..7
        int rem  = wi & 255;
        int s    = rem >> 5;             // k-step 0..7
        int lane = rem & 31;
        int gid  = lane >> 2, tig = lane & 3;
        int pl   = rbl * 16 + gid;
        int k2   = s * 8 + tig;          // bf16-pair index of k0 = s*16 + tig*2
        float i1 = invsm[pl], i2 = invsm[pl + 8];
        uint4 o;
        o.x = scl2(s1u[k2    ][pl    ], i1);
        o.y = scl2(s1u[k2    ][pl + 8], i2);
        o.z = scl2(s1u[k2 + 4][pl    ], i1);
        o.w = scl2(s1u[k2 + 4][pl + 8], i2);
        int rb = blockIdx.x * 8 + rbl;
        g_Apack[((b * NROWBLK + rb) * 8 + s) * 32 + lane] = o;
    }
}

// ---------------- kernel 2: pack B fragments as uint4 (2 k-steps per entry) --------
__global__ void __launch_bounds__(256) k_packB(const float* __restrict__ z2) {
    int g = blockIdx.x * 256 + threadIdx.x;       // 0..32767
    int b   = g >> 14;
    int r   = g & 16383;
    int it  = r >> 10;
    int idx = r & 1023;
    int nb  = idx >> 7;
    int s2  = (idx >> 5) & 3;
    int lane = idx & 31;
    int gid = lane >> 2, tig = lane & 3;
    int n  = nb * 8 + gid;
    int pq = LAST0 + it * 64 + n;
    float inv = g_inv2[b * NPIX + pq] * SCALE_L2;
    const float* zp = z2 + (size_t)b * CDIM * NPIX + pq;
    int k0 = s2 * 32 + tig * 2;
    uint4 o;
    o.x = pack2(zp[(size_t)(k0     ) * NPIX] * inv, zp[(size_t)(k0 +  1) * NPIX] * inv);
    o.y = pack2(zp[(size_t)(k0 +  8) * NPIX] * inv, zp[(size_t)(k0 +  9) * NPIX] * inv);
    o.z = pack2(zp[(size_t)(k0 + 16) * NPIX] * inv, zp[(size_t)(k0 + 17) * NPIX] * inv);
    o.w = pack2(zp[(size_t)(k0 + 24) * NPIX] * inv, zp[(size_t)(k0 + 25) * NPIX] * inv);
    g_Bpack[g] = o;
}

// ---------------- kernel 3: bf16 GEMM, 4 blocks/SM via smem-spilled A fragments -----
__global__ void __launch_bounds__(128, 4) k_main(const int* __restrict__ labels,
                                                 float* __restrict__ out) {
    const int b    = blockIdx.y;
    const int row0 = blockIdx.x * 128;
    const int tid  = threadIdx.x;      // 0..127
    const int w    = tid >> 5;         // 0..3
    const int lane = tid & 31;
    const int gid  = lane >> 2, tig = lane & 3;

    __shared__ uint4 Bsm[2][1024];   // double-buffered 16KB B tiles
    __shared__ uint4 Asp[4][128];    // smem spill: a1 odd k-step fragments [w][s2*32+lane]
    __shared__ int   labsm[1024];
    __shared__ float warpsum[4];

    // labels of last chunk -> shared (vectorized, 128 threads x 2)
    {
        const uint4* lp = (const uint4*)(labels + b * NPIX + LAST0);
        ((uint4*)labsm)[tid]       = lp[tid];
        ((uint4*)labsm)[tid + 128] = lp[tid + 128];
    }

    // A fragments for this warp's 32 rows (2 rowblocks).
    // a0[0..7] in regs; a1 even k-steps in regs; a1 odd k-steps spilled to smem.
    const int rb0 = blockIdx.x * 8 + w * 2;
    uint4 a0[8], a1e[4];
    const uint4* Ap = g_Apack + ((size_t)(b * NROWBLK + rb0) * 8) * 32 + lane;
#pragma unroll
    for (int s = 0; s < 8; s++) a0[s] = Ap[s * 32];
#pragma unroll
    for (int s2 = 0; s2 < 4; s2++) {
        a1e[s2] = Ap[256 + (2 * s2) * 32];
        Asp[w][s2 * 32 + lane] = Ap[256 + (2 * s2 + 1) * 32];  // own slot; no sync needed
    }

    const int r0  = row0 + w * 32 + gid;
    const int lr0 = labels[b * NPIX + r0];
    const int lr1 = labels[b * NPIX + r0 + 8];
    const int lr2 = labels[b * NPIX + r0 + 16];
    const int lr3 = labels[b * NPIX + r0 + 24];

    float sxw  = 0.f;                                   // per-thread sum of masked logits
    float sep0 = 0.f, sep1 = 0.f, sep2 = 0.f, sep3 = 0.f;  // per-row-pair exp sums

    // 4 independent mma chains (consumed one nb later, epilogue-first)
    float eA0=0.f,eA1=0.f,eA2=0.f,eA3=0.f, oA0=0.f,oA1=0.f,oA2=0.f,oA3=0.f;
    float eB0=0.f,eB1=0.f,eB2=0.f,eB3=0.f, oB0=0.f,oB1=0.f,oB2=0.f,oB3=0.f;
    int2  lcp = make_int2(0, 0);

    const uint4* Bp = g_Bpack + b * 16384;

    // prefetch tile 0 (1024 uint4 by 128 threads)
    {
        unsigned sd = (unsigned)__cvta_generic_to_shared(&Bsm[0][0]);
#pragma unroll
        for (int i = 0; i < 8; i++)
            CP16(sd + (tid + 128 * i) * 16, Bp + tid + 128 * i);
        CPCOMMIT();
    }

    for (int it = 0; it < 16; it++) {
        const int buf = it & 1;
        CPWAIT0();
        __syncthreads();   // also orders: all reads of buf (prev it) before this prefetch
        if (it < 15) {
            unsigned sd = (unsigned)__cvta_generic_to_shared(&Bsm[buf ^ 1][0]);
            const uint4* src = Bp + (it + 1) * 1024;
#pragma unroll
            for (int i = 0; i < 8; i++)
                CP16(sd + (tid + 128 * i) * 16, src + tid + 128 * i);
            CPCOMMIT();
        }

        const uint4* Bb = &Bsm[buf][0];
#pragma unroll
        for (int nb = 0; nb < 8; nb++) {
            // (1) epilogue for the previous nb (chain results completed long ago)
            if (it + nb > 0) EPILOGUE_CH(lcp);
            // (2) re-arm chains and issue this nb's 16 mmas
            eA0=0.f;eA1=0.f;eA2=0.f;eA3=0.f; oA0=0.f;oA1=0.f;oA2=0.f;oA3=0.f;
            eB0=0.f;eB1=0.f;eB2=0.f;eB3=0.f; oB0=0.f;oB1=0.f;oB2=0.f;oB3=0.f;
#pragma unroll
            for (int s2 = 0; s2 < 4; s2++) {
                uint4 bf  = Bb[(nb * 4 + s2) * 32 + lane];
                uint4 a1o = Asp[w][s2 * 32 + lane];
                MMA_BF16(eA0, eA1, eA2, eA3, a0[2 * s2],     bf.x, bf.y);
                MMA_BF16(eB0, eB1, eB2, eB3, a1e[s2],        bf.x, bf.y);
                MMA_BF16(oA0, oA1, oA2, oA3, a0[2 * s2 + 1], bf.z, bf.w);
                MMA_BF16(oB0, oB1, oB2, oB3, a1o,            bf.z, bf.w);
            }
            // (3) capture this nb's column labels for the next epilogue
            lcp = ((const int2*)labsm)[it * 32 + nb * 4 + tig];
        }
        // no trailing barrier: next iteration's leading __syncthreads orders
        // these buf reads before the prefetch that overwrites buf.
    }

    // drain: epilogue for the final nb
    EPILOGUE_CH(lcp);

    // per-row exp sums: reduce across the 4 lanes sharing each row
#pragma unroll
    for (int o = 1; o <= 2; o <<= 1) {
        sep0 += __shfl_xor_sync(~0u, sep0, o);
        sep1 += __shfl_xor_sync(~0u, sep1, o);
        sep2 += __shfl_xor_sync(~0u, sep2, o);
        sep3 += __shfl_xor_sync(~0u, sep3, o);
    }

    float v = 0.f;
    if (tig == 0) {
        float p0 = g_posl2[b * NPIX + r0];
        float p1 = g_posl2[b * NPIX + r0 + 8];
        float p2 = g_posl2[b * NPIX + r0 + 16];
        float p3 = g_posl2[b * NPIX + r0 + 24];
        float t0 = sep0 + ex2(p0);
        float t1 = sep1 + ex2(p1);
        float t2 = sep2 + ex2(p2);
        float t3 = sep3 + ex2(p3);
        v = (__log2f(t0) + __log2f(t1) + __log2f(t2) + __log2f(t3))
            - (p0 + p1 + p2 + p3) * (1.0f / 1025.0f);
    }
    v -= sxw * (1.0f / 1025.0f);   // per-thread sum of masked logits
#pragma unroll
    for (int o = 16; o; o >>= 1) v += __shfl_xor_sync(~0u, v, o);
    if (lane == 0) warpsum[w] = LN2F * v;
    __syncthreads();
    if (tid == 0) {
        float ts = warpsum[0] + warpsum[1] + warpsum[2] + warpsum[3];
        atomicAdd(&g_acc, (double)ts);
        __threadfence();
        unsigned done = atomicAdd(&g_done, 1u) + 1u;
        if (done == gridDim.x * gridDim.y) {
            double total = atomicAdd(&g_acc, 0.0);   // coherent read after all adds
            out[0] = (float)(total / (double)(BATCH * NPIX));
        }
    }
}

// ---------------- launch ----------------
extern "C" void kernel_launch(void* const* d_in, const int* in_sizes, int n_in,
                              void* d_out, int out_size) {
    const float* z1     = (const float*)d_in[0];
    const float* z2     = (const float*)d_in[1];
    const int*   labels = (const int*)d_in[2];
    (void)in_sizes; (void)n_in; (void)out_size;

    dim3 g1(NPIX / 128, BATCH);
    k_norm_pack<<<g1, 256>>>(z1, z2);
    k_packB<<<128, 256>>>(z2);
    dim3 g2(NPIX / 128, BATCH);
    k_main<<<g2, 128>>>(labels, (float*)d_out);
}